// round 8
// baseline (speedup 1.0000x reference)
#include <cuda_runtime.h>
#include <cstddef>

#define HH 16
#define DD 1024
#define KD 64
#define NN 4096
#define MM 4096

// Scratch (__device__ globals: the allowed no-malloc workaround)
static __device__ float g_Q[(size_t)HH * NN * KD];   // [h][n][64]
static __device__ float g_K[(size_t)HH * MM * KD];   // [h][m][64]
static __device__ float g_V[(size_t)HH * MM * KD];   // [h][m][64]
static __device__ float g_O[(size_t)NN * (HH * KD)]; // [n][h*64+v]
static __device__ unsigned g_mbits[(size_t)NN * (MM / 32)]; // bit-packed mask (2MB)

typedef unsigned long long u64;

// ---- packed fp32x2 helpers (FFMA2 path: only reachable via PTX) ----------
__device__ __forceinline__ u64 dup2(float x) {
    u64 r; unsigned xi = __float_as_uint(x);
    asm("mov.b64 %0, {%1, %1};" : "=l"(r) : "r"(xi));
    return r;
}
__device__ __forceinline__ void ffma2(u64& d, u64 a, u64 b) {
    asm("fma.rn.f32x2 %0, %1, %2, %0;" : "+l"(d) : "l"(a), "l"(b));
}
__device__ __forceinline__ void fmul2(u64& d, u64 b) {
    asm("mul.rn.f32x2 %0, %0, %1;" : "+l"(d) : "l"(b));
}
__device__ __forceinline__ float f2lo(u64 v) { return __uint_as_float((unsigned)v); }
__device__ __forceinline__ float f2hi(u64 v) { return __uint_as_float((unsigned)(v >> 32)); }

// ---------------------------------------------------------------------------
// Bit-pack mask: one u32 word = 32 mask ints along m.
// ---------------------------------------------------------------------------
__global__ __launch_bounds__(256) void pack_mask(const int* __restrict__ mask,
                                                 unsigned* __restrict__ bits)
{
    int idx = blockIdx.x * 256 + threadIdx.x;        // 0 .. N*128-1
    const int* p = mask + (size_t)idx * 32;
    unsigned b = 0;
#pragma unroll
    for (int u = 0; u < 8; u++) {
        int4 m = ((const int4*)p)[u];
        b |= (unsigned)(m.x != 0) << (u * 4 + 0);
        b |= (unsigned)(m.y != 0) << (u * 4 + 1);
        b |= (unsigned)(m.z != 0) << (u * 4 + 2);
        b |= (unsigned)(m.w != 0) << (u * 4 + 3);
    }
    bits[idx] = b;
}

// ---------------------------------------------------------------------------
// Fused fp32 GEMM: C[128 x 128] = A[128 x K] * [W1 | W2] (two 64-wide panels).
// (unchanged from R6 — FMA-bound per wavefront analysis)
// ---------------------------------------------------------------------------
__global__ __launch_bounds__(256) void gemm2(
    const float* __restrict__ A, int lda,
    const float* __restrict__ W1b, const float* __restrict__ W2b, long wStride, int ldw,
    float* __restrict__ C1b, float* __restrict__ C2b, long cStride, int ldc, int K)
{
    __shared__ float At[32 * 132];   // [kk][rotated row]
    __shared__ float Ws[32 * 136];   // [kk][128 cols: W1 | W2]

    const int tid = threadIdx.x;
    const int tx  = tid & 15;
    const int ty  = tid >> 4;
    const int c0  = tx * 8;
    const int r0  = ty * 8;
    const int row0 = blockIdx.x * 128;
    const float* W1 = W1b + (long)blockIdx.y * wStride;
    const float* W2 = W2b + (long)blockIdx.y * wStride;

    u64 acc[4][8];
#pragma unroll
    for (int i = 0; i < 4; i++)
#pragma unroll
        for (int j = 0; j < 8; j++) acc[i][j] = 0ull;

    for (int kt = 0; kt < K; kt += 32) {
#pragma unroll
        for (int u = 0; u < 4; u++) {
            int idx = tid + u * 256;
            int r   = idx >> 3;
            int kv  = idx & 7;
            float4 v = *(const float4*)(A + (size_t)(row0 + r) * lda + kt + kv * 4);
            int rr = (r + kv * 4) & 127;
            At[(kv * 4 + 0) * 132 + rr] = v.x;
            At[(kv * 4 + 1) * 132 + rr] = v.y;
            At[(kv * 4 + 2) * 132 + rr] = v.z;
            At[(kv * 4 + 3) * 132 + rr] = v.w;
        }
#pragma unroll
        for (int u = 0; u < 4; u++) {
            int idx  = tid + u * 256;
            int half = idx >> 9;
            int kk   = (idx >> 4) & 31;
            int cv   = idx & 15;
            const float* src = (half ? W2 : W1) + (size_t)(kt + kk) * ldw + cv * 4;
            *(float4*)(Ws + kk * 136 + half * 64 + cv * 4) = *(const float4*)src;
        }
        __syncthreads();

#pragma unroll 2
        for (int kk4 = 0; kk4 < 8; kk4++) {
            int ra = (r0 + kk4 * 4) & 127;
            int rb = (r0 + 4 + kk4 * 4) & 127;
#pragma unroll
            for (int s = 0; s < 4; s++) {
                int kk = kk4 * 4 + s;
                ulonglong2 qa = *(const ulonglong2*)(At + kk * 132 + ra);
                ulonglong2 qb = *(const ulonglong2*)(At + kk * 132 + rb);
                float4 w0 = *(const float4*)(Ws + kk * 136 + c0);
                float4 w1 = *(const float4*)(Ws + kk * 136 + c0 + 4);
                u64 d0 = dup2(w0.x), d1 = dup2(w0.y), d2 = dup2(w0.z), d3 = dup2(w0.w);
                u64 d4 = dup2(w1.x), d5 = dup2(w1.y), d6 = dup2(w1.z), d7 = dup2(w1.w);
                ffma2(acc[0][0], qa.x, d0); ffma2(acc[0][1], qa.x, d1);
                ffma2(acc[0][2], qa.x, d2); ffma2(acc[0][3], qa.x, d3);
                ffma2(acc[0][4], qa.x, d4); ffma2(acc[0][5], qa.x, d5);
                ffma2(acc[0][6], qa.x, d6); ffma2(acc[0][7], qa.x, d7);
                ffma2(acc[1][0], qa.y, d0); ffma2(acc[1][1], qa.y, d1);
                ffma2(acc[1][2], qa.y, d2); ffma2(acc[1][3], qa.y, d3);
                ffma2(acc[1][4], qa.y, d4); ffma2(acc[1][5], qa.y, d5);
                ffma2(acc[1][6], qa.y, d6); ffma2(acc[1][7], qa.y, d7);
                ffma2(acc[2][0], qb.x, d0); ffma2(acc[2][1], qb.x, d1);
                ffma2(acc[2][2], qb.x, d2); ffma2(acc[2][3], qb.x, d3);
                ffma2(acc[2][4], qb.x, d4); ffma2(acc[2][5], qb.x, d5);
                ffma2(acc[2][6], qb.x, d6); ffma2(acc[2][7], qb.x, d7);
                ffma2(acc[3][0], qb.y, d0); ffma2(acc[3][1], qb.y, d1);
                ffma2(acc[3][2], qb.y, d2); ffma2(acc[3][3], qb.y, d3);
                ffma2(acc[3][4], qb.y, d4); ffma2(acc[3][5], qb.y, d5);
                ffma2(acc[3][6], qb.y, d6); ffma2(acc[3][7], qb.y, d7);
            }
        }
        __syncthreads();
    }

    float* Cp = (tx < 8)
        ? (C1b + (long)blockIdx.y * cStride + c0)
        : (C2b + (long)blockIdx.y * cStride + (c0 - 64));
#pragma unroll
    for (int i2 = 0; i2 < 4; i2++) {
        float* rlo = Cp + (size_t)(row0 + r0 + 2 * i2) * ldc;
        float* rhi = Cp + (size_t)(row0 + r0 + 2 * i2 + 1) * ldc;
        *(float4*)(rlo)     = make_float4(f2lo(acc[i2][0]), f2lo(acc[i2][1]), f2lo(acc[i2][2]), f2lo(acc[i2][3]));
        *(float4*)(rlo + 4) = make_float4(f2lo(acc[i2][4]), f2lo(acc[i2][5]), f2lo(acc[i2][6]), f2lo(acc[i2][7]));
        *(float4*)(rhi)     = make_float4(f2hi(acc[i2][0]), f2hi(acc[i2][1]), f2hi(acc[i2][2]), f2hi(acc[i2][3]));
        *(float4*)(rhi + 4) = make_float4(f2hi(acc[i2][4]), f2hi(acc[i2][5]), f2hi(acc[i2][6]), f2hi(acc[i2][7]));
    }
}

// ---------------------------------------------------------------------------
// Flash attention fp32, BM=64 x BN=64, 256 threads, 3 CTAs/SM.
// Warp tile 32 rows x 16 cols (lane = 8 lr x 4 lc) -> minimal smem bytes/FMA.
// Row softmax spans 4 warps: warps exchange slice maxima through smem each
// tile (consistent-max protocol), so every Pt entry shares one scaling and PV
// may sum all jm; the row denominators l are merged once at the end.
// P stored transposed (Pt[jm][row]) -> conflict-free LDS.128 in PV.
// ---------------------------------------------------------------------------
__global__ __launch_bounds__(256, 3) void attn_kernel(void)
{
    extern __shared__ float sm[];
    float* Qt  = sm;                  // [64 kd][68 rows]
    float* Kt  = Qt + 64 * 68;        // [64 kd][68 rotated cols]
    float* Vs  = Kt + 64 * 68;        // [64 jm][68 v-cols]
    float* Pt  = Vs + 64 * 68;        // [64 jm][68 rows]  (transposed P)
    float* Msl = Pt + 64 * 68;        // [64 rows][4 slices]: tile max / final l

    const int tid  = threadIdx.x;
    const int lane = tid & 31;
    const int wrp  = tid >> 5;
    const int lr   = lane >> 2;
    const int lc   = lane & 3;
    const int wr   = wrp & 1;         // 2 row-groups of warps
    const int wc   = wrp >> 1;        // 4 col-slices of warps
    const int r0   = wr * 32 + lr * 4;
    const int c0   = wc * 16 + lc * 4;
    const int shift = c0 & 31;
    const int h  = blockIdx.x;        // heads fastest -> K/V + mask L2 reuse
    const int n0 = blockIdx.y * 64;

    const float* Qh = g_Q + (size_t)h * NN * KD;
    const float* Kh = g_K + (size_t)h * MM * KD;
    const float* Vh = g_V + (size_t)h * MM * KD;

    // Load Q tile 64x64, kd-major (one-time; unrotated), tid-mapped
#pragma unroll
    for (int u = 0; u < 4; u++) {
        int idx = tid + u * 256;
        int r   = idx >> 4;           // 0..63
        int kv  = idx & 15;
        float4 v = *(const float4*)(Qh + (size_t)(n0 + r) * KD + kv * 4);
        Qt[(kv * 4 + 0) * 68 + r] = v.x;
        Qt[(kv * 4 + 1) * 68 + r] = v.y;
        Qt[(kv * 4 + 2) * 68 + r] = v.z;
        Qt[(kv * 4 + 3) * 68 + r] = v.w;
    }

    float mrow[4], lrow[4];
    u64 o2[4][2];                     // [row][v-col pair]
#pragma unroll
    for (int i = 0; i < 4; i++) {
        mrow[i] = -1e30f; lrow[i] = 0.0f;
        o2[i][0] = 0ull; o2[i][1] = 0ull;
    }

    for (int mt = 0; mt < MM; mt += 64) {
        __syncthreads();              // prior PV readers of Vs/Pt, QK readers of Kt done

        // Load K (kd-major, rotated) + V (row-major) 64x64 tiles, tid-mapped
#pragma unroll
        for (int u = 0; u < 4; u++) {
            int idx = tid + u * 256;
            int j   = idx >> 4;       // 0..63
            int kv  = idx & 15;
            float4 kf = *(const float4*)(Kh + (size_t)(mt + j) * KD + kv * 4);
            int jr = (j + kv * 4) & 63;
            Kt[(kv * 4 + 0) * 68 + jr] = kf.x;
            Kt[(kv * 4 + 1) * 68 + jr] = kf.y;
            Kt[(kv * 4 + 2) * 68 + jr] = kf.z;
            Kt[(kv * 4 + 3) * 68 + jr] = kf.w;
            *(float4*)(Vs + j * 68 + kv * 4) =
                *(const float4*)(Vh + (size_t)(mt + j) * KD + kv * 4);
        }

        // Prefetch mask bits (consumed after QK -> LDG latency hidden)
        unsigned mw[4];
        {
            int widx = (mt + c0) >> 5;
#pragma unroll
            for (int i = 0; i < 4; i++)
                mw[i] = g_mbits[(size_t)(n0 + r0 + i) * (MM / 32) + widx];
        }
        __syncthreads();

        // ---- S = Q K^T (row-pair packed) ----
        u64 s2[2][4];
#pragma unroll
        for (int i = 0; i < 2; i++)
#pragma unroll
            for (int j = 0; j < 4; j++) s2[i][j] = 0ull;

#pragma unroll 4
        for (int kd4 = 0; kd4 < 16; kd4++) {
            int cc = (c0 + kd4 * 4) & 63;   // rotated col start
#pragma unroll
            for (int s = 0; s < 4; s++) {
                int kd = kd4 * 4 + s;
                ulonglong2 qa = *(const ulonglong2*)(Qt + kd * 68 + r0);
                float4 kf = *(const float4*)(Kt + kd * 68 + cc);
                u64 k0 = dup2(kf.x), k1 = dup2(kf.y), k2 = dup2(kf.z), k3 = dup2(kf.w);
                ffma2(s2[0][0], qa.x, k0); ffma2(s2[0][1], qa.x, k1);
                ffma2(s2[0][2], qa.x, k2); ffma2(s2[0][3], qa.x, k3);
                ffma2(s2[1][0], qa.y, k0); ffma2(s2[1][1], qa.y, k1);
                ffma2(s2[1][2], qa.y, k2); ffma2(s2[1][3], qa.y, k3);
            }
        }

        // ---- phase 1: mask + per-slice max -> smem ----
        float pv[4][4];
#pragma unroll
        for (int i = 0; i < 4; i++) {
            const int p = i >> 1, sub = i & 1;
            float v0 = sub ? f2hi(s2[p][0]) : f2lo(s2[p][0]);
            float v1 = sub ? f2hi(s2[p][1]) : f2lo(s2[p][1]);
            float v2 = sub ? f2hi(s2[p][2]) : f2lo(s2[p][2]);
            float v3 = sub ? f2hi(s2[p][3]) : f2lo(s2[p][3]);
            unsigned bits = (mw[i] >> shift) & 0xFu;
            if (!(bits & 1u)) v0 = -1e30f;
            if (!(bits & 2u)) v1 = -1e30f;
            if (!(bits & 4u)) v2 = -1e30f;
            if (!(bits & 8u)) v3 = -1e30f;
            float mx = fmaxf(fmaxf(v0, v1), fmaxf(v2, v3));
            mx = fmaxf(mx, __shfl_xor_sync(0xffffffffu, mx, 1));
            mx = fmaxf(mx, __shfl_xor_sync(0xffffffffu, mx, 2));
            if (lc == 0) Msl[(r0 + i) * 4 + wc] = mx;
            pv[i][0] = v0; pv[i][1] = v1; pv[i][2] = v2; pv[i][3] = v3;
        }
        __syncthreads();

        // ---- phase 2: consistent tile max -> exp, Pt store, l update ----
#pragma unroll
        for (int i = 0; i < 4; i++) {
            float4 mv = *(const float4*)(Msl + (r0 + i) * 4);
            float mx = fmaxf(fmaxf(mv.x, mv.y), fmaxf(mv.z, mv.w));
            float mnew = fmaxf(mrow[i], mx);
            float sc   = __expf(mrow[i] - mnew);
            mrow[i] = mnew;
            float e0 = __expf(pv[i][0] - mnew);
            float e1 = __expf(pv[i][1] - mnew);
            float e2 = __expf(pv[i][2] - mnew);
            float e3 = __expf(pv[i][3] - mnew);
            float rs = (e0 + e1) + (e2 + e3);
            rs += __shfl_xor_sync(0xffffffffu, rs, 1);
            rs += __shfl_xor_sync(0xffffffffu, rs, 2);
            lrow[i] = lrow[i] * sc + rs;        // slice-partial l (merged at end)
            u64 scd = dup2(sc);
            fmul2(o2[i][0], scd);
            fmul2(o2[i][1], scd);
            Pt[(c0 + 0) * 68 + r0 + i] = e0;
            Pt[(c0 + 1) * 68 + r0 + i] = e1;
            Pt[(c0 + 2) * 68 + r0 + i] = e2;
            Pt[(c0 + 3) * 68 + r0 + i] = e3;
        }
        __syncthreads();

        // ---- O += P V : p as conflict-free LDS.128 over 4 rows ----
#pragma unroll 4
        for (int jm = 0; jm < 64; jm++) {
            float4 p4 = *(const float4*)(Pt + jm * 68 + r0);
            ulonglong2 vv = *(const ulonglong2*)(Vs + jm * 68 + c0);
            u64 p0 = dup2(p4.x), p1 = dup2(p4.y), p2 = dup2(p4.z), p3 = dup2(p4.w);
            ffma2(o2[0][0], vv.x, p0); ffma2(o2[0][1], vv.y, p0);
            ffma2(o2[1][0], vv.x, p1); ffma2(o2[1][1], vv.y, p1);
            ffma2(o2[2][0], vv.x, p2); ffma2(o2[2][1], vv.y, p2);
            ffma2(o2[3][0], vv.x, p3); ffma2(o2[3][1], vv.y, p3);
        }
    }

    // ---- merge slice-partial l across the 4 wc warps, write O/l ----
    __syncthreads();
    if (lc == 0) {
#pragma unroll
        for (int i = 0; i < 4; i++)
            Msl[(r0 + i) * 4 + wc] = lrow[i];
    }
    __syncthreads();
#pragma unroll
    for (int i = 0; i < 4; i++) {
        float4 lv = *(const float4*)(Msl + (r0 + i) * 4);
        float inv = 1.0f / ((lv.x + lv.y) + (lv.z + lv.w));
        *(float4*)(g_O + (size_t)(n0 + r0 + i) * (HH * KD) + h * KD + c0) =
            make_float4(f2lo(o2[i][0]) * inv, f2hi(o2[i][0]) * inv,
                        f2lo(o2[i][1]) * inv, f2hi(o2[i][1]) * inv);
    }
}

// ---------------------------------------------------------------------------
extern "C" void kernel_launch(void* const* d_in, const int* in_sizes, int n_in,
                              void* d_out, int out_size)
{
    const float* X    = (const float*)d_in[0];
    const float* Mm   = (const float*)d_in[1];
    const int*   mask = (const int*)  d_in[2];
    const float* Wq   = (const float*)d_in[3];
    const float* Wk   = (const float*)d_in[4];
    const float* Wv   = (const float*)d_in[5];
    const float* Wo   = (const float*)d_in[6];
    float*       Y    = (float*)d_out;

    float *qp, *kp, *vp, *op;
    unsigned* mbp;
    cudaGetSymbolAddress((void**)&qp, g_Q);
    cudaGetSymbolAddress((void**)&kp, g_K);
    cudaGetSymbolAddress((void**)&vp, g_V);
    cudaGetSymbolAddress((void**)&op, g_O);
    cudaGetSymbolAddress((void**)&mbp, g_mbits);

    const int SMEM_ATTN = (4 * 64 * 68 + 256) * (int)sizeof(float);   // 70656 B
    cudaFuncSetAttribute(attn_kernel, cudaFuncAttributeMaxDynamicSharedMemorySize, SMEM_ATTN);

    dim3 blk(256);
    const long DK = (long)DD * KD, NK = (long)NN * KD, MK = (long)MM * KD;

    // Bit-pack mask
    pack_mask<<<(NN * (MM / 32)) / 256, blk>>>(mask, mbp);
    // Q: head pairs (2h, 2h+1) share the X tile
    gemm2<<<dim3(NN / 128, HH / 2), blk>>>(X, DD, Wq, Wq + DK, 2 * DK, KD,
                                           qp, qp + NK, 2 * NK, KD, DD);
    // K|V fused: same M tile feeds both projections of head h
    gemm2<<<dim3(MM / 128, HH), blk>>>(Mm, DD, Wk, Wv, DK, KD,
                                       kp, vp, MK, KD, DD);
    // Attention (heads fastest -> K/V + mask-bit L2 reuse)
    attn_kernel<<<dim3(HH, NN / 64), blk, SMEM_ATTN>>>();
    // Y = O @ Wo_flat: col-block pairs (128y, 128y+64)
    gemm2<<<dim3(NN / 128, (HH * KD) / 128), blk>>>(op, HH * KD, Wo, Wo + 64, 128, HH * KD,
                                                    Y, Y + 64, 128, HH * KD, DD);
}